// round 14
// baseline (speedup 1.0000x reference)
#include <cuda_runtime.h>
#include <cuda_bf16.h>
#include <math.h>
#include <stdint.h>

#define NI 100000
#define DD 512
#define DA 256
#define NC 4
#define KSEL 1000
#define NSEL 15
#define MAXCAND 20000
#define MAXEQ 4096
#define TILES 782
#define ROWS_PAD (TILES * 128)

#define FS_OFF 0
#define YP_OFF 400000
#define YH_OFF 400004
#define REF_OFF 400005
#define IL_OFF 900005

__device__ __align__(16) float g_det_logit[NI * NC];
__device__ __align__(16) float g_cls_score[NI * NC];
__device__ float g_ref1[NI * 5];
__device__ float g_ref2[NI * 5];
__device__ float g_mean[NI];

__device__ __align__(16) __nv_bfloat16 g_h_hi[(size_t)ROWS_PAD * DD];
__device__ __align__(16) __nv_bfloat16 g_h_lo[(size_t)ROWS_PAD * DD];
__device__ __align__(16) __nv_bfloat16 g_w_hi[512 * 512];
__device__ __align__(16) __nv_bfloat16 g_w_lo[512 * 512];
__device__ __align__(16) __nv_bfloat16 g_ws_hi[32 * 512];
__device__ __align__(16) __nv_bfloat16 g_ws_lo[32 * 512];

__device__ float    g_det_sum[NC];
__device__ unsigned g_fs_min_enc[NC];
__device__ unsigned g_fs_max_enc[NC];
__device__ float    g_fs_sum[NC];

__device__ int      g_include[NSEL];
__device__ unsigned g_hist[NSEL][2048];
__device__ unsigned g_prefix[NSEL];
__device__ int      g_kRem[NSEL];
__device__ int      g_cand_s[MAXCAND];
__device__ int      g_cand_i[MAXCAND];
__device__ int      g_cand_cnt;
__device__ int      g_eq_idx[NSEL][MAXEQ];
__device__ int      g_eq_cnt[NSEL];
__device__ float    g_num[3];
__device__ int      g_den[3];

__device__ __forceinline__ unsigned encf(float f) {
    unsigned u = __float_as_uint(f);
    return (u & 0x80000000u) ? ~u : (u | 0x80000000u);
}
__device__ __forceinline__ float decf(unsigned k) {
    unsigned u = (k & 0x80000000u) ? (k & 0x7FFFFFFFu) : ~k;
    return __uint_as_float(u);
}

__device__ __forceinline__ uint32_t smem_u32(const void *p) {
    uint32_t a;
    asm("{ .reg .u64 t; cvta.to.shared.u64 t, %1; cvt.u32.u64 %0, t; }" : "=r"(a) : "l"(p));
    return a;
}
__device__ __forceinline__ void cpasync16(uint32_t dst, const void *src) {
    asm volatile("cp.async.cg.shared.global [%0], [%1], 16;"
                 :: "r"(dst), "l"(__cvta_generic_to_global(src)) : "memory");
}

// ---- pure-FMA fast math ----
__device__ __forceinline__ float exp_fast(float x) {
    float t = x * 1.4426950408889634f;
    t = fminf(fmaxf(t, -126.f), 126.f);
    float r = rintf(t);
    float f = t - r;
    float p = 1.5403530393e-4f;
    p = fmaf(p, f, 1.3333558146e-3f);
    p = fmaf(p, f, 9.6181291076e-3f);
    p = fmaf(p, f, 5.5504108665e-2f);
    p = fmaf(p, f, 2.4022650696e-1f);
    p = fmaf(p, f, 6.9314718056e-1f);
    p = fmaf(p, f, 1.0f);
    int e = (int)r;
    return p * __int_as_float((e + 127) << 23);
}
__device__ __forceinline__ float rcp_fast(float x) {
    float r = __uint_as_float(0x7EF311C3u - __float_as_uint(x));
    r = r * (2.0f - x * r);
    r = r * (2.0f - x * r);
    r = r * (2.0f - x * r);
    return r;
}

// ---------------- k_init ----------------
__global__ void k_init(const int *__restrict__ label) {
    int t = threadIdx.x;
    if (t < NC) {
        g_det_sum[t] = 0.f;
        g_fs_min_enc[t] = 0xFFFFFFFFu; g_fs_max_enc[t] = 0u; g_fs_sum[t] = 0.f;
    }
    if (t < NSEL) {
        g_prefix[t] = 0u; g_kRem[t] = KSEL; g_eq_cnt[t] = 0;
        int inc;
        if (t == 4) inc = 1;
        else {
            int c = (t < 4) ? t : (t - 5) % 5;
            inc = (c == NC) ? 1 : ((label[0] == c || label[1] == c) ? 1 : 0);
        }
        g_include[t] = inc;
    }
    if (t < 3) { g_num[t] = 0.f; g_den[t] = 0; }
    if (t == 0) g_cand_cnt = 0;
}

// ---------------- k_split: h -> padded bf16 hi/lo ----------------
__global__ __launch_bounds__(256) void k_split(const float *__restrict__ h) {
    size_t i = ((size_t)blockIdx.x * blockDim.x + threadIdx.x) * 8;
    const size_t total = (size_t)ROWS_PAD * DD;
    if (i >= total) return;
    float f[8];
    if (i < (size_t)NI * DD) {
        float4 v0 = *(const float4 *)&h[i];
        float4 v1 = *(const float4 *)&h[i + 4];
        f[0]=v0.x; f[1]=v0.y; f[2]=v0.z; f[3]=v0.w;
        f[4]=v1.x; f[5]=v1.y; f[6]=v1.z; f[7]=v1.w;
    } else {
#pragma unroll
        for (int j = 0; j < 8; j++) f[j] = 0.f;
    }
    __nv_bfloat16 hi[8], lo[8];
#pragma unroll
    for (int j = 0; j < 8; j++) {
        hi[j] = __float2bfloat16(f[j]);
        lo[j] = __float2bfloat16(f[j] - __bfloat162float(hi[j]));
    }
    *(uint4 *)&g_h_hi[i] = *(uint4 *)hi;
    *(uint4 *)&g_h_lo[i] = *(uint4 *)lo;
}

// ---------------- k_wsplit: weights -> bf16 hi/lo; det_logit := bc; zero g_hist ----------------
__global__ __launch_bounds__(256) void k_wsplit(const float *__restrict__ Wa, const float *__restrict__ Wb,
                                                const float *__restrict__ Wcls, const float *__restrict__ Wr,
                                                const float *__restrict__ bc) {
    int i = blockIdx.x * blockDim.x + threadIdx.x;
    if (i < 512 * 512) {
        int n = i >> 9, k = i & 511;
        float v = (n < DA) ? Wa[k * DA + n] : Wb[k * DA + (n - DA)];
        __nv_bfloat16 hi = __float2bfloat16(v);
        g_w_hi[i] = hi;
        g_w_lo[i] = __float2bfloat16(v - __bfloat162float(hi));
    } else if (i < 512 * 512 + 32 * 512) {
        int j = i - 512 * 512;
        int n = j >> 9, k = j & 511;
        float v = 0.f;
        if (n < 4) v = Wcls[k * 4 + n];
        else if (n < 19) {
            int cc = n - 4, r = cc / 5, e = cc % 5;
            v = Wr[((size_t)r * 512 + k) * 5 + e];
        }
        __nv_bfloat16 hi = __float2bfloat16(v);
        g_ws_hi[j] = hi;
        g_ws_lo[j] = __float2bfloat16(v - __bfloat162float(hi));
    }
    if (i < NI) {
        float4 v = make_float4(bc[0], bc[1], bc[2], bc[3]);
        *(float4 *)&g_det_logit[i * 4] = v;
    }
    if (i < NSEL * 2048) ((unsigned *)g_hist)[i] = 0u;
}

// ---------------- K1: unified GEMM, cp.async double-buffered ----------------
#define BUFSTR 40960
#define OFF_AH 0
#define OFF_AL 10240
#define OFF_BH 20480
#define OFF_BL 30720
#define K1_SMEM (2 * BUFSTR)

#define LDM4(R, addr) \
    asm volatile("ldmatrix.sync.aligned.m8n8.x4.shared.b16 {%0,%1,%2,%3}, [%4];" \
        : "=r"((R)[0]), "=r"((R)[1]), "=r"((R)[2]), "=r"((R)[3]) : "r"(addr))

#define MMA(dp, A, b0, b1) \
    asm volatile("mma.sync.aligned.m16n8k16.row.col.f32.bf16.bf16.f32 " \
        "{%0,%1,%2,%3}, {%4,%5,%6,%7}, {%8,%9}, {%0,%1,%2,%3};" \
        : "+f"((dp)[0]), "+f"((dp)[1]), "+f"((dp)[2]), "+f"((dp)[3]) \
        : "r"((A)[0]), "r"((A)[1]), "r"((A)[2]), "r"((A)[3]), "r"(b0), "r"(b1))

#define K1_LOAD(kt, buf) do { \
    uint32_t base_ = sb + (uint32_t)(buf) * BUFSTR; \
    _Pragma("unroll") \
    for (int ii_ = 0; ii_ < 4; ii_++) { \
        int cid_ = tid + ii_ * 256; \
        int pl_ = cid_ >> 9; \
        int rem_ = cid_ & 511; \
        int row_ = rem_ >> 2, ch_ = rem_ & 3; \
        const __nv_bfloat16 *ap_ = (pl_ ? g_h_lo : g_h_hi) + (size_t)(rowBase + row_) * 512 + (size_t)(kt) * 32 + ch_ * 8; \
        cpasync16(base_ + OFF_AH + (uint32_t)pl_ * 10240u + row_ * 80 + ch_ * 16, ap_); \
    } \
    if (smallP) { \
        int br_ = tid >> 3; \
        int rem_ = tid & 7; \
        int pl_ = rem_ >> 2, bch_ = rem_ & 3; \
        const __nv_bfloat16 *bp_ = (pl_ ? g_ws_lo : g_ws_hi) + (size_t)br_ * 512 + (size_t)(kt) * 32 + bch_ * 8; \
        cpasync16(base_ + OFF_BH + (uint32_t)pl_ * 10240u + br_ * 80 + bch_ * 16, bp_); \
    } else { \
        _Pragma("unroll") \
        for (int ii_ = 0; ii_ < 4; ii_++) { \
            int cid_ = tid + ii_ * 256; \
            int pl_ = cid_ >> 9; \
            int rem_ = cid_ & 511; \
            int br_ = rem_ >> 2, bch_ = rem_ & 3; \
            int ng_ = (br_ < 64) ? (cb * 64 + br_) : (256 + cb * 64 + (br_ - 64)); \
            const __nv_bfloat16 *bp_ = (pl_ ? g_w_lo : g_w_hi) + (size_t)ng_ * 512 + (size_t)(kt) * 32 + bch_ * 8; \
            cpasync16(base_ + OFF_BH + (uint32_t)pl_ * 10240u + br_ * 80 + bch_ * 16, bp_); \
        } \
    } \
    asm volatile("cp.async.commit_group;" ::: "memory"); \
} while (0)

__global__ __launch_bounds__(256, 2) void k1_mma(
    const float *__restrict__ ba, const float *__restrict__ bb,
    const float *__restrict__ Wc,
    const float *__restrict__ bcls, const float *__restrict__ br,
    float *__restrict__ outRef) {
    extern __shared__ char smem[];
    __shared__ float bSm[19];
    uint32_t sb = smem_u32(smem);
    int tid = threadIdx.x;
    int l = tid & 31, w = tid >> 5;
    int wm = w & 3, wn = w >> 2;
    int cb = blockIdx.x % 5;
    int rowBase = (blockIdx.x / 5) * 128;
    bool smallP = (cb == 4);

    float d[64];
#pragma unroll
    for (int i = 0; i < 64; i++) d[i] = 0.f;

    if (tid < 19) bSm[tid] = (tid < 4) ? bcls[tid] : br[tid - 4];

    uint32_t aRowOff = (uint32_t)((wm * 32 + (l & 15)) * 80 + (l >> 4) * 16);
    uint32_t bRowOff = (uint32_t)((wn * 64 + (l & 7) + ((l >> 4) & 1) * 8) * 80 + ((l >> 3) & 1) * 16);
    uint32_t bRowOffS = (uint32_t)((wn * 16 + (l & 7) + ((l >> 4) & 1) * 8) * 80 + ((l >> 3) & 1) * 16);

    K1_LOAD(0, 0);
    for (int kt = 0; kt < 16; kt++) {
        int buf = kt & 1;
        asm volatile("cp.async.wait_group 0;" ::: "memory");
        __syncthreads();
        if (kt < 15) K1_LOAD(kt + 1, buf ^ 1);

        uint32_t base = sb + (uint32_t)buf * BUFSTR;
        uint32_t aHiB = base + OFF_AH + aRowOff;
        uint32_t aLoB = base + OFF_AL + aRowOff;
        if (smallP) {
            uint32_t bsH = base + OFF_BH + bRowOffS;
            uint32_t bsL = base + OFF_BL + bRowOffS;
#pragma unroll
            for (int kb = 0; kb < 2; kb++) {
                uint32_t BsH[4], BsL[4], A0[4], A1[4], L0[4], L1[4];
                LDM4(BsH, bsH + kb * 32);
                LDM4(BsL, bsL + kb * 32);
                LDM4(A0, aHiB + kb * 32);
                LDM4(A1, aHiB + 1280 + kb * 32);
                LDM4(L0, aLoB + kb * 32);
                LDM4(L1, aLoB + 1280 + kb * 32);
                // pass 1: hi * Bh  (4 independent accumulators)
                MMA(&d[0],  A0, BsH[0], BsH[1]);
                MMA(&d[4],  A0, BsH[2], BsH[3]);
                MMA(&d[8],  A1, BsH[0], BsH[1]);
                MMA(&d[12], A1, BsH[2], BsH[3]);
                // pass 2: hi * Bl
                MMA(&d[0],  A0, BsL[0], BsL[1]);
                MMA(&d[4],  A0, BsL[2], BsL[3]);
                MMA(&d[8],  A1, BsL[0], BsL[1]);
                MMA(&d[12], A1, BsL[2], BsL[3]);
                // pass 3: lo * Bh
                MMA(&d[0],  L0, BsH[0], BsH[1]);
                MMA(&d[4],  L0, BsH[2], BsH[3]);
                MMA(&d[8],  L1, BsH[0], BsH[1]);
                MMA(&d[12], L1, BsH[2], BsH[3]);
            }
        } else {
            uint32_t bHiB = base + OFF_BH + bRowOff;
            uint32_t bLoB = base + OFF_BL + bRowOff;
#pragma unroll
            for (int kb = 0; kb < 2; kb++) {
                uint32_t Bh[16], Bl[16], A0[4], A1[4], L0[4], L1[4];
                LDM4(&Bh[0],  bHiB + kb * 32);
                LDM4(&Bh[4],  bHiB + 1280 + kb * 32);
                LDM4(&Bh[8],  bHiB + 2560 + kb * 32);
                LDM4(&Bh[12], bHiB + 3840 + kb * 32);
                LDM4(&Bl[0],  bLoB + kb * 32);
                LDM4(&Bl[4],  bLoB + 1280 + kb * 32);
                LDM4(&Bl[8],  bLoB + 2560 + kb * 32);
                LDM4(&Bl[12], bLoB + 3840 + kb * 32);
                LDM4(A0, aHiB + kb * 32);
                LDM4(A1, aHiB + 1280 + kb * 32);
                LDM4(L0, aLoB + kb * 32);
                LDM4(L1, aLoB + 1280 + kb * 32);
                // pass 1: hi * Bh — 16 independent accumulators
#pragma unroll
                for (int mf = 0; mf < 2; mf++) {
                    const uint32_t *A = mf ? A1 : A0;
#pragma unroll
                    for (int nf = 0; nf < 8; nf++)
                        MMA(&d[(mf * 8 + nf) * 4], A, Bh[nf * 2], Bh[nf * 2 + 1]);
                }
                // pass 2: hi * Bl
#pragma unroll
                for (int mf = 0; mf < 2; mf++) {
                    const uint32_t *A = mf ? A1 : A0;
#pragma unroll
                    for (int nf = 0; nf < 8; nf++)
                        MMA(&d[(mf * 8 + nf) * 4], A, Bl[nf * 2], Bl[nf * 2 + 1]);
                }
                // pass 3: lo * Bh
#pragma unroll
                for (int mf = 0; mf < 2; mf++) {
                    const uint32_t *A = mf ? L1 : L0;
#pragma unroll
                    for (int nf = 0; nf < 8; nf++)
                        MMA(&d[(mf * 8 + nf) * 4], A, Bh[nf * 2], Bh[nf * 2 + 1]);
                }
            }
        }
    }
    __syncthreads();

    if (smallP) {
        float *plane = (float *)smem;  // [128][26]
#pragma unroll
        for (int mf = 0; mf < 2; mf++)
#pragma unroll
            for (int nf = 0; nf < 2; nf++)
#pragma unroll
                for (int e = 0; e < 4; e++) {
                    int row = wm * 32 + mf * 16 + (l >> 2) + ((e >> 1) << 3);
                    int col = wn * 16 + nf * 8 + ((l & 3) << 1) + (e & 1);
                    if (col < 19) plane[row * 26 + col] = d[(mf * 2 + nf) * 4 + e];
                }
        __syncthreads();
        if (l < 16) {
            int row = w * 16 + l;
            int grow = rowBase + row;
            if (grow < NI) {
                float lg[19];
#pragma unroll
                for (int c = 0; c < 19; c++) lg[c] = plane[row * 26 + c] + bSm[c];
                float m = fmaxf(fmaxf(lg[0], lg[1]), fmaxf(lg[2], lg[3]));
                float e0 = expf(lg[0]-m), e1 = expf(lg[1]-m), e2 = expf(lg[2]-m), e3 = expf(lg[3]-m);
                float inv = 1.f / (e0 + e1 + e2 + e3);
                g_cls_score[grow*4+0]=e0*inv; g_cls_score[grow*4+1]=e1*inv;
                g_cls_score[grow*4+2]=e2*inv; g_cls_score[grow*4+3]=e3*inv;
#pragma unroll
                for (int r = 0; r < 3; r++) {
                    float lv[5]; float mm = -1e30f;
#pragma unroll
                    for (int e = 0; e < 5; e++) { lv[e] = lg[4+5*r+e]; mm = fmaxf(mm, lv[e]); }
                    float s = 0.f;
#pragma unroll
                    for (int e = 0; e < 5; e++) { lv[e] = expf(lv[e]-mm); s += lv[e]; }
                    float iv = 1.f / s;
                    float *dst = (r==0) ? &g_ref1[(size_t)grow*5] : (r==1) ? &g_ref2[(size_t)grow*5] : &outRef[(size_t)grow*5];
#pragma unroll
                    for (int e = 0; e < 5; e++) dst[e] = lv[e] * iv;
                }
            }
        }
        return;
    }

    float *plane = (float *)smem;  // [128][72]
    if (wn == 0) {
#pragma unroll
        for (int mf = 0; mf < 2; mf++)
#pragma unroll
            for (int nf = 0; nf < 8; nf++)
#pragma unroll
                for (int e = 0; e < 4; e++) {
                    int row = wm * 32 + mf * 16 + (l >> 2) + ((e >> 1) << 3);
                    int col = nf * 8 + ((l & 3) << 1) + (e & 1);
                    float x = d[(mf * 8 + nf) * 4 + e] + __ldg(&ba[cb * 64 + col]);
                    float E2 = exp_fast(2.f * x);
                    plane[row * 72 + col] = (E2 - 1.f) * rcp_fast(E2 + 1.f);
                }
    }
    __syncthreads();
    if (wn == 1) {
        float acc[4][4];
#pragma unroll
        for (int ri = 0; ri < 4; ri++)
#pragma unroll
            for (int c = 0; c < 4; c++) acc[ri][c] = 0.f;
#pragma unroll
        for (int mf = 0; mf < 2; mf++)
#pragma unroll
            for (int nf = 0; nf < 8; nf++)
#pragma unroll
                for (int e = 0; e < 4; e++) {
                    int ri = mf * 2 + (e >> 1);
                    int row = wm * 32 + mf * 16 + (l >> 2) + ((e >> 1) << 3);
                    int jloc = nf * 8 + ((l & 3) << 1) + (e & 1);
                    int jg = cb * 64 + jloc;
                    float x = d[(mf * 8 + nf) * 4 + e] + __ldg(&bb[jg]);
                    float Eb = exp_fast(x);
                    float s = Eb * rcp_fast(Eb + 1.f);
                    float p = plane[row * 72 + jloc] * s;
#pragma unroll
                    for (int c = 0; c < 4; c++)
                        acc[ri][c] = fmaf(p, __ldg(&Wc[jg * 4 + c]), acc[ri][c]);
                }
#pragma unroll
        for (int off = 1; off <= 2; off <<= 1)
#pragma unroll
            for (int ri = 0; ri < 4; ri++)
#pragma unroll
                for (int c = 0; c < 4; c++)
                    acc[ri][c] += __shfl_xor_sync(0xffffffffu, acc[ri][c], off);
        if ((l & 3) == 0) {
#pragma unroll
            for (int ri = 0; ri < 4; ri++) {
                int grow = rowBase + wm * 32 + (ri >> 1) * 16 + (l >> 2) + (ri & 1) * 8;
                if (grow < NI) {
#pragma unroll
                    for (int c = 0; c < 4; c++)
                        atomicAdd(&g_det_logit[grow * 4 + c], acc[ri][c]);
                }
            }
        }
    }
}

// ---------------- k_detsum ----------------
__global__ void k_detsum() {
    float s[NC] = {0.f, 0.f, 0.f, 0.f};
    for (int i = blockIdx.x * blockDim.x + threadIdx.x; i < NI; i += gridDim.x * blockDim.x) {
        float4 v = *(const float4 *)&g_det_logit[i * 4];
        s[0]+=expf(v.x); s[1]+=expf(v.y); s[2]+=expf(v.z); s[3]+=expf(v.w);
    }
#pragma unroll
    for (int off = 16; off; off >>= 1)
#pragma unroll
        for (int c = 0; c < NC; c++) s[c] += __shfl_xor_sync(0xffffffffu, s[c], off);
    __shared__ float sm[8][NC];
    int w = threadIdx.x >> 5, l = threadIdx.x & 31;
    if (l == 0) for (int c = 0; c < NC; c++) sm[w][c] = s[c];
    __syncthreads();
    if (threadIdx.x == 0)
        for (int c = 0; c < NC; c++) {
            float ss = 0.f;
            for (int ww = 0; ww < 8; ww++) ss += sm[ww][c];
            atomicAdd(&g_det_sum[c], ss);
        }
}

__global__ void k_fscore(float *__restrict__ out) {
    float inv[NC];
#pragma unroll
    for (int c = 0; c < NC; c++) inv[c] = 1.f / g_det_sum[c];
    float fmn[NC], fmx[NC], fsm[NC];
#pragma unroll
    for (int c = 0; c < NC; c++) { fmn[c] = 1e30f; fmx[c] = -1e30f; fsm[c] = 0.f; }
    for (int i = blockIdx.x * blockDim.x + threadIdx.x; i < NI; i += gridDim.x * blockDim.x) {
        float4 dl = *(const float4 *)&g_det_logit[i * 4];
        float4 cs = *(const float4 *)&g_cls_score[i * 4];
        float f0 = cs.x * (expf(dl.x) * inv[0]);
        float f1 = cs.y * (expf(dl.y) * inv[1]);
        float f2 = cs.z * (expf(dl.z) * inv[2]);
        float f3 = cs.w * (expf(dl.w) * inv[3]);
        *(float4 *)&out[(size_t)FS_OFF + i * 4] = make_float4(f0, f1, f2, f3);
        g_mean[i] = 0.25f * (f0 + f1 + f2 + f3);
        fmn[0]=fminf(fmn[0],f0); fmx[0]=fmaxf(fmx[0],f0); fsm[0]+=f0;
        fmn[1]=fminf(fmn[1],f1); fmx[1]=fmaxf(fmx[1],f1); fsm[1]+=f1;
        fmn[2]=fminf(fmn[2],f2); fmx[2]=fmaxf(fmx[2],f2); fsm[2]+=f2;
        fmn[3]=fminf(fmn[3],f3); fmx[3]=fmaxf(fmx[3],f3); fsm[3]+=f3;
    }
#pragma unroll
    for (int off = 16; off; off >>= 1)
#pragma unroll
        for (int c = 0; c < NC; c++) {
            fmn[c] = fminf(fmn[c], __shfl_xor_sync(0xffffffffu, fmn[c], off));
            fmx[c] = fmaxf(fmx[c], __shfl_xor_sync(0xffffffffu, fmx[c], off));
            fsm[c] += __shfl_xor_sync(0xffffffffu, fsm[c], off);
        }
    __shared__ float smn[8][NC], smx[8][NC], ssm[8][NC];
    int w = threadIdx.x >> 5, l = threadIdx.x & 31;
    if (l == 0) for (int c = 0; c < NC; c++) { smn[w][c]=fmn[c]; smx[w][c]=fmx[c]; ssm[w][c]=fsm[c]; }
    __syncthreads();
    if (threadIdx.x == 0)
        for (int c = 0; c < NC; c++) {
            float a = smn[0][c], b = smx[0][c], s = ssm[0][c];
            for (int ww = 1; ww < 8; ww++) { a=fminf(a,smn[ww][c]); b=fmaxf(b,smx[ww][c]); s+=ssm[ww][c]; }
            atomicMin(&g_fs_min_enc[c], encf(a));
            atomicMax(&g_fs_max_enc[c], encf(b));
            atomicAdd(&g_fs_sum[c], s);
        }
}

__device__ __forceinline__ void load_vals(const float *__restrict__ outFS, int i, float v[NSEL]) {
    float4 fs = *(const float4 *)&outFS[i * 4];
    v[0]=fs.x; v[1]=fs.y; v[2]=fs.z; v[3]=fs.w;
    v[4] = -g_mean[i];
#pragma unroll
    for (int e = 0; e < 5; e++) v[5+e] = g_ref1[(size_t)i*5+e];
#pragma unroll
    for (int e = 0; e < 5; e++) v[10+e] = g_ref2[(size_t)i*5+e];
}

// 3-pass radix select: bit widths 11/11/10, shifts 21/10/0
__global__ void k_hist(const float *__restrict__ outFS, int pass) {
    extern __shared__ unsigned histS[];
    __shared__ unsigned prefS[NSEL];
    __shared__ int incS[NSEL];
    int tid = threadIdx.x;
    int bins = (pass == 2) ? 1024 : 2048;
    int shift = (pass == 0) ? 21 : (pass == 1) ? 10 : 0;
    int prevsh = (pass == 1) ? 21 : 10;
    for (int i = tid; i < NSEL * bins; i += blockDim.x) histS[i] = 0u;
    if (tid < NSEL) { prefS[tid] = g_prefix[tid]; incS[tid] = g_include[tid]; }
    __syncthreads();
    for (int i = blockIdx.x * blockDim.x + tid; i < NI; i += gridDim.x * blockDim.x) {
        float v[NSEL];
        load_vals(outFS, i, v);
#pragma unroll
        for (int s = 0; s < NSEL; s++) {
            unsigned bucket = 0xFFFFFFFFu;
            if (incS[s]) {
                unsigned key = encf(v[s]);
                bool match = (pass == 0) || ((key >> prevsh) == (prefS[s] >> prevsh));
                if (match) bucket = (key >> shift) & (unsigned)(bins - 1);
            }
            unsigned mm = __match_any_sync(0xffffffffu, bucket);
            int leader = __ffs(mm) - 1;
            if ((int)(threadIdx.x & 31) == leader && bucket != 0xFFFFFFFFu)
                atomicAdd(&histS[s * bins + bucket], __popc(mm));
        }
    }
    __syncthreads();
    for (int i = tid; i < NSEL * bins; i += blockDim.x)
        if (histS[i]) atomicAdd(&g_hist[i / bins][i % bins], histS[i]);
}

__global__ void k_scan(int pass) {
    int w = threadIdx.x >> 5, l = threadIdx.x & 31;
    int bins = (pass == 2) ? 1024 : 2048;
    int shift = (pass == 0) ? 21 : (pass == 1) ? 10 : 0;
    if (w < NSEL && g_include[w]) {
        int kr = g_kRem[w];
        int chunk = bins >> 5;
        unsigned T = 0;
        for (int j = 0; j < chunk; j++) T += g_hist[w][l * chunk + j];
        unsigned x = T;
#pragma unroll
        for (int off = 1; off < 32; off <<= 1) {
            unsigned y = __shfl_down_sync(0xffffffffu, x, off);
            if (l + off < 32) x += y;
        }
        unsigned S = x - T;
        unsigned total = __shfl_sync(0xffffffffu, x, 0);
        bool has = (S < (unsigned)kr) && (S + T >= (unsigned)kr);
        unsigned bal = __ballot_sync(0xffffffffu, has);
        if (bal) {
            int selL = __ffs(bal) - 1;
            if (l == selL) {
                unsigned cum = S;
                for (int bin = (l + 1) * chunk - 1; bin >= l * chunk; bin--) {
                    unsigned c = g_hist[w][bin];
                    if (cum + c >= (unsigned)kr) {
                        g_prefix[w] |= ((unsigned)bin << shift);
                        g_kRem[w] = kr - (int)cum;
                        break;
                    }
                    cum += c;
                }
            }
        } else if (l == 0) {
            g_kRem[w] = kr - (int)total;
        }
    }
    __syncthreads();
    for (int i = threadIdx.x; i < NSEL * 2048; i += blockDim.x)
        ((unsigned *)g_hist)[i] = 0u;
}

__device__ __forceinline__ bool is_valid(int s, float v, const float *mn, const float *mx) {
    if (s < 4) return ((v - mn[s]) / (mx[s] - mn[s])) > 0.5f;
    else if (s == 4) return (-v) < 0.5f;
    else return v > 0.5f;
}

__global__ void k_gather(const float *__restrict__ outFS) {
    __shared__ float mnS[NC], mxS[NC];
    __shared__ unsigned thrS[NSEL];
    __shared__ int incS[NSEL];
    int tid = threadIdx.x;
    if (tid < NC) { mnS[tid] = decf(g_fs_min_enc[tid]); mxS[tid] = decf(g_fs_max_enc[tid]); }
    if (tid < NSEL) { thrS[tid] = g_prefix[tid]; incS[tid] = g_include[tid]; }
    __syncthreads();
    for (int i = blockIdx.x * blockDim.x + tid; i < NI; i += gridDim.x * blockDim.x) {
        float v[NSEL];
        load_vals(outFS, i, v);
#pragma unroll
        for (int s = 0; s < NSEL; s++) {
            if (!incS[s]) continue;
            unsigned key = encf(v[s]);
            if (key > thrS[s]) {
                if (is_valid(s, v[s], mnS, mxS)) {
                    int g = (s < 5) ? 0 : (s < 10 ? 1 : 2);
                    atomicAdd(&g_den[g], 1);
                    int slot = atomicAdd(&g_cand_cnt, 1);
                    if (slot < MAXCAND) { g_cand_s[slot] = s; g_cand_i[slot] = i; }
                }
            } else if (key == thrS[s]) {
                int slot = atomicAdd(&g_eq_cnt[s], 1);
                if (slot < MAXEQ) g_eq_idx[s][slot] = i;
            }
        }
    }
}

__global__ void k_tie() {
    int warp = threadIdx.x >> 5;
    int lane = threadIdx.x & 31;
    if (warp >= NSEL) return;
    int s = warp;
    if (!g_include[s]) return;
    int m = g_eq_cnt[s];
    if (m > MAXEQ) m = MAXEQ;
    int nt = g_kRem[s];
    if (m <= 0 || nt <= 0) return;
    float v = decf(g_prefix[s]);
    float mn[NC], mx[NC];
#pragma unroll
    for (int c = 0; c < NC; c++) { mn[c] = decf(g_fs_min_enc[c]); mx[c] = decf(g_fs_max_enc[c]); }
    if (!is_valid(s, v, mn, mx)) return;
    int g = (s < 5) ? 0 : (s < 10 ? 1 : 2);
    int prev = -1;
    for (int t = 0; t < nt; t++) {
        int best = 0x7FFFFFFF;
        for (int j = lane; j < m; j += 32) {
            int idx = g_eq_idx[s][j];
            if (idx > prev && idx < best) best = idx;
        }
#pragma unroll
        for (int off = 16; off; off >>= 1)
            best = min(best, __shfl_xor_sync(0xffffffffu, best, off));
        if (best == 0x7FFFFFFF) break;
        if (lane == 0) {
            atomicAdd(&g_den[g], 1);
            int slot = atomicAdd(&g_cand_cnt, 1);
            if (slot < MAXCAND) { g_cand_s[slot] = s; g_cand_i[slot] = best; }
        }
        prev = best;
    }
}

__global__ __launch_bounds__(128) void k_ce(const float *__restrict__ h,
                                            const float *__restrict__ Wr,
                                            const float *__restrict__ br) {
    __shared__ float WrS[3 * DD * 5];
    __shared__ float brS[15];
    __shared__ float red[4][5];
    int tid = threadIdx.x;
    for (int i = tid; i < 3 * DD * 5; i += 128) WrS[i] = Wr[i];
    if (tid < 15) brS[tid] = br[tid];
    __syncthreads();
    int cnt = g_cand_cnt;
    if (cnt > MAXCAND) cnt = MAXCAND;
    int warp = tid >> 5, lane = tid & 31;
    for (int ci = blockIdx.x; ci < cnt; ci += gridDim.x) {
        int s = g_cand_s[ci], i = g_cand_i[ci];
        int r = (s < 5) ? 0 : (s < 10 ? 1 : 2);
        int tgt = (s < 4) ? s : ((s == 4) ? 4 : (s - 5) % 5);
        const float *hr = h + (size_t)i * DD;
        float part[5] = {0.f, 0.f, 0.f, 0.f, 0.f};
#pragma unroll
        for (int t = 0; t < 4; t++) {
            float hv = hr[tid + 128 * t];
            const float *wk = &WrS[r * (DD * 5) + (tid + 128 * t) * 5];
#pragma unroll
            for (int e = 0; e < 5; e++) part[e] = fmaf(hv, wk[e], part[e]);
        }
#pragma unroll
        for (int off = 16; off; off >>= 1)
#pragma unroll
            for (int e = 0; e < 5; e++) part[e] += __shfl_xor_sync(0xffffffffu, part[e], off);
        if (lane == 0)
            for (int e = 0; e < 5; e++) red[warp][e] = part[e];
        __syncthreads();
        if (tid == 0) {
            float lv[5]; float mm = -1e30f;
#pragma unroll
            for (int e = 0; e < 5; e++) {
                lv[e] = red[0][e] + red[1][e] + red[2][e] + red[3][e] + brS[r * 5 + e];
                mm = fmaxf(mm, lv[e]);
            }
            float ss = 0.f;
#pragma unroll
            for (int e = 0; e < 5; e++) ss += expf(lv[e] - mm);
            float ce = logf(ss) + mm - lv[tgt];
            atomicAdd(&g_num[r], ce);
        }
        __syncthreads();
    }
}

__global__ void k_finish(float *__restrict__ out) {
    if (threadIdx.x == 0) {
        float yp[NC];
#pragma unroll
        for (int c = 0; c < NC; c++) {
            float v = g_fs_sum[c];
            v = fminf(fmaxf(v, 1e-10f), 1.f - 1e-10f);
            yp[c] = v;
            out[YP_OFF + c] = v;
        }
        int am = 0;
        for (int c = 1; c < NC; c++)
            if (yp[c] > yp[am]) am = c;
        out[YH_OFF] = (float)am;
        float loss = 0.f;
        for (int g = 0; g < 3; g++) {
            float den = (float)(g_den[g] > 1 ? g_den[g] : 1);
            loss += g_num[g] / den;
        }
        out[IL_OFF] = loss;
    }
}

extern "C" void kernel_launch(void *const *d_in, const int *in_sizes, int n_in,
                              void *d_out, int out_size) {
    const float *h    = (const float *)d_in[0];
    const int   *label= (const int *)d_in[1];
    const float *Wa   = (const float *)d_in[2];
    const float *ba   = (const float *)d_in[3];
    const float *Wb   = (const float *)d_in[4];
    const float *bb   = (const float *)d_in[5];
    const float *Wc   = (const float *)d_in[6];
    const float *bc   = (const float *)d_in[7];
    const float *Wcls = (const float *)d_in[8];
    const float *bcls = (const float *)d_in[9];
    const float *Wr   = (const float *)d_in[10];
    const float *br   = (const float *)d_in[11];
    float *out = (float *)d_out;

    cudaFuncSetAttribute(k1_mma, cudaFuncAttributeMaxDynamicSharedMemorySize, K1_SMEM);
    cudaFuncSetAttribute(k_hist, cudaFuncAttributeMaxDynamicSharedMemorySize, NSEL * 2048 * 4);

    k_init<<<1, 256>>>(label);
    k_wsplit<<<(512 * 512 + 32 * 512 + 255) / 256, 256>>>(Wa, Wb, Wcls, Wr, bc);
    k_split<<<(int)(((size_t)ROWS_PAD * DD / 8 + 255) / 256), 256>>>(h);
    k1_mma<<<TILES * 5, 256, K1_SMEM>>>(ba, bb, Wc, bcls, br, out + REF_OFF);  // 4th -> profiled
    k_detsum<<<256, 256>>>();
    k_fscore<<<256, 256>>>(out);
    for (int pass = 0; pass < 3; pass++) {
        int bins = (pass == 2) ? 1024 : 2048;
        k_hist<<<200, 256, NSEL * bins * 4>>>(out, pass);
        k_scan<<<1, 480>>>(pass);
    }
    k_gather<<<200, 256>>>(out);
    k_tie<<<1, 480>>>();
    k_ce<<<1024, 128>>>(h, Wr, br);
    k_finish<<<1, 1>>>(out);
}

// round 15
// speedup vs baseline: 1.0616x; 1.0616x over previous
#include <cuda_runtime.h>
#include <cuda_bf16.h>
#include <math.h>
#include <stdint.h>

#define NI 100000
#define DD 512
#define DA 256
#define NC 4
#define KSEL 1000
#define NSEL 15
#define MAXCAND 20000
#define MAXEQ 4096
#define TILES 782
#define ROWS_PAD (TILES * 128)

#define FS_OFF 0
#define YP_OFF 400000
#define YH_OFF 400004
#define REF_OFF 400005
#define IL_OFF 900005

__device__ __align__(16) float g_det_logit[NI * NC];
__device__ __align__(16) float g_cls_score[NI * NC];
__device__ float g_ref1[NI * 5];
__device__ float g_ref2[NI * 5];
__device__ float g_mean[NI];

__device__ __align__(16) __nv_bfloat16 g_h_hi[(size_t)ROWS_PAD * DD];
__device__ __align__(16) __nv_bfloat16 g_h_lo[(size_t)ROWS_PAD * DD];
__device__ __align__(16) __nv_bfloat16 g_w_hi[512 * 512];
__device__ __align__(16) __nv_bfloat16 g_w_lo[512 * 512];
__device__ __align__(16) __nv_bfloat16 g_ws_hi[32 * 512];
__device__ __align__(16) __nv_bfloat16 g_ws_lo[32 * 512];

__device__ float    g_det_sum[NC];
__device__ unsigned g_fs_min_enc[NC];
__device__ unsigned g_fs_max_enc[NC];
__device__ float    g_fs_sum[NC];

__device__ int      g_include[NSEL];
__device__ unsigned g_hist[NSEL][2048];
__device__ unsigned g_prefix[NSEL];
__device__ int      g_kRem[NSEL];
__device__ int      g_cand_s[MAXCAND];
__device__ int      g_cand_i[MAXCAND];
__device__ int      g_cand_cnt;
__device__ int      g_eq_idx[NSEL][MAXEQ];
__device__ int      g_eq_cnt[NSEL];
__device__ float    g_num[3];
__device__ int      g_den[3];

__device__ __forceinline__ unsigned encf(float f) {
    unsigned u = __float_as_uint(f);
    return (u & 0x80000000u) ? ~u : (u | 0x80000000u);
}
__device__ __forceinline__ float decf(unsigned k) {
    unsigned u = (k & 0x80000000u) ? (k & 0x7FFFFFFFu) : ~k;
    return __uint_as_float(u);
}

__device__ __forceinline__ uint32_t smem_u32(const void *p) {
    uint32_t a;
    asm("{ .reg .u64 t; cvta.to.shared.u64 t, %1; cvt.u32.u64 %0, t; }" : "=r"(a) : "l"(p));
    return a;
}
__device__ __forceinline__ void cpasync16(uint32_t dst, const void *src) {
    asm volatile("cp.async.cg.shared.global [%0], [%1], 16;"
                 :: "r"(dst), "l"(__cvta_generic_to_global(src)) : "memory");
}

// ---- pure-FMA fast math ----
__device__ __forceinline__ float exp_fast(float x) {
    float t = x * 1.4426950408889634f;
    t = fminf(fmaxf(t, -126.f), 126.f);
    float r = rintf(t);
    float f = t - r;
    float p = 1.5403530393e-4f;
    p = fmaf(p, f, 1.3333558146e-3f);
    p = fmaf(p, f, 9.6181291076e-3f);
    p = fmaf(p, f, 5.5504108665e-2f);
    p = fmaf(p, f, 2.4022650696e-1f);
    p = fmaf(p, f, 6.9314718056e-1f);
    p = fmaf(p, f, 1.0f);
    int e = (int)r;
    return p * __int_as_float((e + 127) << 23);
}
__device__ __forceinline__ float rcp_fast(float x) {
    float r = __uint_as_float(0x7EF311C3u - __float_as_uint(x));
    r = r * (2.0f - x * r);
    r = r * (2.0f - x * r);
    r = r * (2.0f - x * r);
    return r;
}

// ---------------- k_init ----------------
__global__ void k_init(const int *__restrict__ label) {
    int t = threadIdx.x;
    if (t < NC) {
        g_det_sum[t] = 0.f;
        g_fs_min_enc[t] = 0xFFFFFFFFu; g_fs_max_enc[t] = 0u; g_fs_sum[t] = 0.f;
    }
    if (t < NSEL) {
        g_prefix[t] = 0u; g_kRem[t] = KSEL; g_eq_cnt[t] = 0;
        int inc;
        if (t == 4) inc = 1;
        else {
            int c = (t < 4) ? t : (t - 5) % 5;
            inc = (c == NC) ? 1 : ((label[0] == c || label[1] == c) ? 1 : 0);
        }
        g_include[t] = inc;
    }
    if (t < 3) { g_num[t] = 0.f; g_den[t] = 0; }
    if (t == 0) g_cand_cnt = 0;
}

// ---------------- k_split ----------------
__global__ __launch_bounds__(256) void k_split(const float *__restrict__ h) {
    size_t i = ((size_t)blockIdx.x * blockDim.x + threadIdx.x) * 8;
    const size_t total = (size_t)ROWS_PAD * DD;
    if (i >= total) return;
    float f[8];
    if (i < (size_t)NI * DD) {
        float4 v0 = *(const float4 *)&h[i];
        float4 v1 = *(const float4 *)&h[i + 4];
        f[0]=v0.x; f[1]=v0.y; f[2]=v0.z; f[3]=v0.w;
        f[4]=v1.x; f[5]=v1.y; f[6]=v1.z; f[7]=v1.w;
    } else {
#pragma unroll
        for (int j = 0; j < 8; j++) f[j] = 0.f;
    }
    __nv_bfloat16 hi[8], lo[8];
#pragma unroll
    for (int j = 0; j < 8; j++) {
        hi[j] = __float2bfloat16(f[j]);
        lo[j] = __float2bfloat16(f[j] - __bfloat162float(hi[j]));
    }
    *(uint4 *)&g_h_hi[i] = *(uint4 *)hi;
    *(uint4 *)&g_h_lo[i] = *(uint4 *)lo;
}

// ---------------- k_wsplit ----------------
__global__ __launch_bounds__(256) void k_wsplit(const float *__restrict__ Wa, const float *__restrict__ Wb,
                                                const float *__restrict__ Wcls, const float *__restrict__ Wr,
                                                const float *__restrict__ bc) {
    int i = blockIdx.x * blockDim.x + threadIdx.x;
    if (i < 512 * 512) {
        int n = i >> 9, k = i & 511;
        float v = (n < DA) ? Wa[k * DA + n] : Wb[k * DA + (n - DA)];
        __nv_bfloat16 hi = __float2bfloat16(v);
        g_w_hi[i] = hi;
        g_w_lo[i] = __float2bfloat16(v - __bfloat162float(hi));
    } else if (i < 512 * 512 + 32 * 512) {
        int j = i - 512 * 512;
        int n = j >> 9, k = j & 511;
        float v = 0.f;
        if (n < 4) v = Wcls[k * 4 + n];
        else if (n < 19) {
            int cc = n - 4, r = cc / 5, e = cc % 5;
            v = Wr[((size_t)r * 512 + k) * 5 + e];
        }
        __nv_bfloat16 hi = __float2bfloat16(v);
        g_ws_hi[j] = hi;
        g_ws_lo[j] = __float2bfloat16(v - __bfloat162float(hi));
    }
    if (i < NI) {
        float4 v = make_float4(bc[0], bc[1], bc[2], bc[3]);
        *(float4 *)&g_det_logit[i * 4] = v;
    }
    if (i < NSEL * 2048) ((unsigned *)g_hist)[i] = 0u;
}

// ---------------- K1 (R13-exact mainloop) ----------------
#define BUFSTR 40960
#define OFF_AH 0
#define OFF_AL 10240
#define OFF_BH 20480
#define OFF_BL 30720
#define K1_SMEM (2 * BUFSTR)

#define LDM4(R, addr) \
    asm volatile("ldmatrix.sync.aligned.m8n8.x4.shared.b16 {%0,%1,%2,%3}, [%4];" \
        : "=r"((R)[0]), "=r"((R)[1]), "=r"((R)[2]), "=r"((R)[3]) : "r"(addr))

#define MMA(dp, A, b0, b1) \
    asm volatile("mma.sync.aligned.m16n8k16.row.col.f32.bf16.bf16.f32 " \
        "{%0,%1,%2,%3}, {%4,%5,%6,%7}, {%8,%9}, {%0,%1,%2,%3};" \
        : "+f"((dp)[0]), "+f"((dp)[1]), "+f"((dp)[2]), "+f"((dp)[3]) \
        : "r"((A)[0]), "r"((A)[1]), "r"((A)[2]), "r"((A)[3]), "r"(b0), "r"(b1))

#define K1_LOAD(kt, buf) do { \
    uint32_t base_ = sb + (uint32_t)(buf) * BUFSTR; \
    _Pragma("unroll") \
    for (int ii_ = 0; ii_ < 4; ii_++) { \
        int cid_ = tid + ii_ * 256; \
        int pl_ = cid_ >> 9; \
        int rem_ = cid_ & 511; \
        int row_ = rem_ >> 2, ch_ = rem_ & 3; \
        const __nv_bfloat16 *ap_ = (pl_ ? g_h_lo : g_h_hi) + (size_t)(rowBase + row_) * 512 + (size_t)(kt) * 32 + ch_ * 8; \
        cpasync16(base_ + OFF_AH + (uint32_t)pl_ * 10240u + row_ * 80 + ch_ * 16, ap_); \
    } \
    if (smallP) { \
        int br_ = tid >> 3; \
        int rem_ = tid & 7; \
        int pl_ = rem_ >> 2, bch_ = rem_ & 3; \
        const __nv_bfloat16 *bp_ = (pl_ ? g_ws_lo : g_ws_hi) + (size_t)br_ * 512 + (size_t)(kt) * 32 + bch_ * 8; \
        cpasync16(base_ + OFF_BH + (uint32_t)pl_ * 10240u + br_ * 80 + bch_ * 16, bp_); \
    } else { \
        _Pragma("unroll") \
        for (int ii_ = 0; ii_ < 4; ii_++) { \
            int cid_ = tid + ii_ * 256; \
            int pl_ = cid_ >> 9; \
            int rem_ = cid_ & 511; \
            int br_ = rem_ >> 2, bch_ = rem_ & 3; \
            int ng_ = (br_ < 64) ? (cb * 64 + br_) : (256 + cb * 64 + (br_ - 64)); \
            const __nv_bfloat16 *bp_ = (pl_ ? g_w_lo : g_w_hi) + (size_t)ng_ * 512 + (size_t)(kt) * 32 + bch_ * 8; \
            cpasync16(base_ + OFF_BH + (uint32_t)pl_ * 10240u + br_ * 80 + bch_ * 16, bp_); \
        } \
    } \
    asm volatile("cp.async.commit_group;" ::: "memory"); \
} while (0)

__global__ __launch_bounds__(256, 2) void k1_mma(
    const float *__restrict__ ba, const float *__restrict__ bb,
    const float *__restrict__ Wc,
    const float *__restrict__ bcls, const float *__restrict__ br,
    float *__restrict__ outRef) {
    extern __shared__ char smem[];
    __shared__ float bSm[19];
    uint32_t sb = smem_u32(smem);
    int tid = threadIdx.x;
    int l = tid & 31, w = tid >> 5;
    int wm = w & 3, wn = w >> 2;
    int cb = blockIdx.x % 5;
    int rowBase = (blockIdx.x / 5) * 128;
    bool smallP = (cb == 4);

    float d[64];
#pragma unroll
    for (int i = 0; i < 64; i++) d[i] = 0.f;

    if (tid < 19) bSm[tid] = (tid < 4) ? bcls[tid] : br[tid - 4];

    uint32_t aRowOff = (uint32_t)((wm * 32 + (l & 15)) * 80 + (l >> 4) * 16);
    uint32_t bRowOff = (uint32_t)((wn * 64 + (l & 7) + ((l >> 4) & 1) * 8) * 80 + ((l >> 3) & 1) * 16);
    uint32_t bRowOffS = (uint32_t)((wn * 16 + (l & 7) + ((l >> 4) & 1) * 8) * 80 + ((l >> 3) & 1) * 16);

    K1_LOAD(0, 0);
    for (int kt = 0; kt < 16; kt++) {
        int buf = kt & 1;
        asm volatile("cp.async.wait_group 0;" ::: "memory");
        __syncthreads();
        if (kt < 15) K1_LOAD(kt + 1, buf ^ 1);

        uint32_t base = sb + (uint32_t)buf * BUFSTR;
        uint32_t aHiB = base + OFF_AH + aRowOff;
        uint32_t aLoB = base + OFF_AL + aRowOff;
        if (smallP) {
            uint32_t bsH = base + OFF_BH + bRowOffS;
            uint32_t bsL = base + OFF_BL + bRowOffS;
#pragma unroll
            for (int kb = 0; kb < 2; kb++) {
                uint32_t BsH[4], BsL[4], A0[4], A1[4];
                LDM4(BsH, bsH + kb * 32);
                LDM4(BsL, bsL + kb * 32);
                LDM4(A0, aHiB + kb * 32);
                LDM4(A1, aHiB + 1280 + kb * 32);
#pragma unroll
                for (int mf = 0; mf < 2; mf++) {
                    const uint32_t *A = mf ? A1 : A0;
                    MMA(&d[(mf * 2 + 0) * 4], A, BsH[0], BsH[1]);
                    MMA(&d[(mf * 2 + 1) * 4], A, BsH[2], BsH[3]);
                    MMA(&d[(mf * 2 + 0) * 4], A, BsL[0], BsL[1]);
                    MMA(&d[(mf * 2 + 1) * 4], A, BsL[2], BsL[3]);
                }
                LDM4(A0, aLoB + kb * 32);
                LDM4(A1, aLoB + 1280 + kb * 32);
#pragma unroll
                for (int mf = 0; mf < 2; mf++) {
                    const uint32_t *A = mf ? A1 : A0;
                    MMA(&d[(mf * 2 + 0) * 4], A, BsH[0], BsH[1]);
                    MMA(&d[(mf * 2 + 1) * 4], A, BsH[2], BsH[3]);
                }
            }
        } else {
            uint32_t bHiB = base + OFF_BH + bRowOff;
            uint32_t bLoB = base + OFF_BL + bRowOff;
#pragma unroll
            for (int kb = 0; kb < 2; kb++) {
                uint32_t Bh[16], Bl[16], A0[4], A1[4];
                LDM4(&Bh[0],  bHiB + kb * 32);
                LDM4(&Bh[4],  bHiB + 1280 + kb * 32);
                LDM4(&Bh[8],  bHiB + 2560 + kb * 32);
                LDM4(&Bh[12], bHiB + 3840 + kb * 32);
                LDM4(&Bl[0],  bLoB + kb * 32);
                LDM4(&Bl[4],  bLoB + 1280 + kb * 32);
                LDM4(&Bl[8],  bLoB + 2560 + kb * 32);
                LDM4(&Bl[12], bLoB + 3840 + kb * 32);
                LDM4(A0, aHiB + kb * 32);
                LDM4(A1, aHiB + 1280 + kb * 32);
#pragma unroll
                for (int mf = 0; mf < 2; mf++) {
                    const uint32_t *A = mf ? A1 : A0;
#pragma unroll
                    for (int nf = 0; nf < 8; nf++) {
                        MMA(&d[(mf * 8 + nf) * 4], A, Bh[nf * 2], Bh[nf * 2 + 1]);
                        MMA(&d[(mf * 8 + nf) * 4], A, Bl[nf * 2], Bl[nf * 2 + 1]);
                    }
                }
                LDM4(A0, aLoB + kb * 32);
                LDM4(A1, aLoB + 1280 + kb * 32);
#pragma unroll
                for (int mf = 0; mf < 2; mf++) {
                    const uint32_t *A = mf ? A1 : A0;
#pragma unroll
                    for (int nf = 0; nf < 8; nf++)
                        MMA(&d[(mf * 8 + nf) * 4], A, Bh[nf * 2], Bh[nf * 2 + 1]);
                }
            }
        }
    }
    __syncthreads();

    if (smallP) {
        float *plane = (float *)smem;  // [128][26]
#pragma unroll
        for (int mf = 0; mf < 2; mf++)
#pragma unroll
            for (int nf = 0; nf < 2; nf++)
#pragma unroll
                for (int e = 0; e < 4; e++) {
                    int row = wm * 32 + mf * 16 + (l >> 2) + ((e >> 1) << 3);
                    int col = wn * 16 + nf * 8 + ((l & 3) << 1) + (e & 1);
                    if (col < 19) plane[row * 26 + col] = d[(mf * 2 + nf) * 4 + e];
                }
        __syncthreads();
        if (l < 16) {
            int row = w * 16 + l;
            int grow = rowBase + row;
            if (grow < NI) {
                float lg[19];
#pragma unroll
                for (int c = 0; c < 19; c++) lg[c] = plane[row * 26 + c] + bSm[c];
                float m = fmaxf(fmaxf(lg[0], lg[1]), fmaxf(lg[2], lg[3]));
                float e0 = expf(lg[0]-m), e1 = expf(lg[1]-m), e2 = expf(lg[2]-m), e3 = expf(lg[3]-m);
                float inv = 1.f / (e0 + e1 + e2 + e3);
                g_cls_score[grow*4+0]=e0*inv; g_cls_score[grow*4+1]=e1*inv;
                g_cls_score[grow*4+2]=e2*inv; g_cls_score[grow*4+3]=e3*inv;
#pragma unroll
                for (int r = 0; r < 3; r++) {
                    float lv[5]; float mm = -1e30f;
#pragma unroll
                    for (int e = 0; e < 5; e++) { lv[e] = lg[4+5*r+e]; mm = fmaxf(mm, lv[e]); }
                    float s = 0.f;
#pragma unroll
                    for (int e = 0; e < 5; e++) { lv[e] = expf(lv[e]-mm); s += lv[e]; }
                    float iv = 1.f / s;
                    float *dst = (r==0) ? &g_ref1[(size_t)grow*5] : (r==1) ? &g_ref2[(size_t)grow*5] : &outRef[(size_t)grow*5];
#pragma unroll
                    for (int e = 0; e < 5; e++) dst[e] = lv[e] * iv;
                }
            }
        }
        return;
    }

    float *plane = (float *)smem;  // [128][72]
    if (wn == 0) {
#pragma unroll
        for (int mf = 0; mf < 2; mf++)
#pragma unroll
            for (int nf = 0; nf < 8; nf++)
#pragma unroll
                for (int e = 0; e < 4; e++) {
                    int row = wm * 32 + mf * 16 + (l >> 2) + ((e >> 1) << 3);
                    int col = nf * 8 + ((l & 3) << 1) + (e & 1);
                    float x = d[(mf * 8 + nf) * 4 + e] + __ldg(&ba[cb * 64 + col]);
                    float E2 = exp_fast(2.f * x);
                    plane[row * 72 + col] = (E2 - 1.f) * rcp_fast(E2 + 1.f);
                }
    }
    __syncthreads();
    if (wn == 1) {
        float acc[4][4];
#pragma unroll
        for (int ri = 0; ri < 4; ri++)
#pragma unroll
            for (int c = 0; c < 4; c++) acc[ri][c] = 0.f;
#pragma unroll
        for (int mf = 0; mf < 2; mf++)
#pragma unroll
            for (int nf = 0; nf < 8; nf++)
#pragma unroll
                for (int e = 0; e < 4; e++) {
                    int ri = mf * 2 + (e >> 1);
                    int row = wm * 32 + mf * 16 + (l >> 2) + ((e >> 1) << 3);
                    int jloc = nf * 8 + ((l & 3) << 1) + (e & 1);
                    int jg = cb * 64 + jloc;
                    float x = d[(mf * 8 + nf) * 4 + e] + __ldg(&bb[jg]);
                    float Eb = exp_fast(x);
                    float s = Eb * rcp_fast(Eb + 1.f);
                    float p = plane[row * 72 + jloc] * s;
#pragma unroll
                    for (int c = 0; c < 4; c++)
                        acc[ri][c] = fmaf(p, __ldg(&Wc[jg * 4 + c]), acc[ri][c]);
                }
#pragma unroll
        for (int off = 1; off <= 2; off <<= 1)
#pragma unroll
            for (int ri = 0; ri < 4; ri++)
#pragma unroll
                for (int c = 0; c < 4; c++)
                    acc[ri][c] += __shfl_xor_sync(0xffffffffu, acc[ri][c], off);
        if ((l & 3) == 0) {
#pragma unroll
            for (int ri = 0; ri < 4; ri++) {
                int grow = rowBase + wm * 32 + (ri >> 1) * 16 + (l >> 2) + (ri & 1) * 8;
                if (grow < NI) {
#pragma unroll
                    for (int c = 0; c < 4; c++)
                        atomicAdd(&g_det_logit[grow * 4 + c], acc[ri][c]);
                }
            }
        }
    }
}

// ---------------- k_detsum ----------------
__global__ void k_detsum() {
    float s[NC] = {0.f, 0.f, 0.f, 0.f};
    for (int i = blockIdx.x * blockDim.x + threadIdx.x; i < NI; i += gridDim.x * blockDim.x) {
        float4 v = *(const float4 *)&g_det_logit[i * 4];
        s[0]+=expf(v.x); s[1]+=expf(v.y); s[2]+=expf(v.z); s[3]+=expf(v.w);
    }
#pragma unroll
    for (int off = 16; off; off >>= 1)
#pragma unroll
        for (int c = 0; c < NC; c++) s[c] += __shfl_xor_sync(0xffffffffu, s[c], off);
    __shared__ float sm[8][NC];
    int w = threadIdx.x >> 5, l = threadIdx.x & 31;
    if (l == 0) for (int c = 0; c < NC; c++) sm[w][c] = s[c];
    __syncthreads();
    if (threadIdx.x == 0)
        for (int c = 0; c < NC; c++) {
            float ss = 0.f;
            for (int ww = 0; ww < 8; ww++) ss += sm[ww][c];
            atomicAdd(&g_det_sum[c], ss);
        }
}

// ---------------- k_fscore + fused radix pass 0 (bins=2048, shift=21) ----------------
__global__ void k_fscore(float *__restrict__ out) {
    extern __shared__ unsigned histS[];   // NSEL * 2048
    __shared__ int incS[NSEL];
    int tid = threadIdx.x;
    for (int i = tid; i < NSEL * 2048; i += blockDim.x) histS[i] = 0u;
    if (tid < NSEL) incS[tid] = g_include[tid];
    __syncthreads();

    float inv[NC];
#pragma unroll
    for (int c = 0; c < NC; c++) inv[c] = 1.f / g_det_sum[c];
    float fmn[NC], fmx[NC], fsm[NC];
#pragma unroll
    for (int c = 0; c < NC; c++) { fmn[c] = 1e30f; fmx[c] = -1e30f; fsm[c] = 0.f; }
    for (int i = blockIdx.x * blockDim.x + tid; i < NI; i += gridDim.x * blockDim.x) {
        float4 dl = *(const float4 *)&g_det_logit[i * 4];
        float4 cs = *(const float4 *)&g_cls_score[i * 4];
        float v[NSEL];
        v[0] = cs.x * (expf(dl.x) * inv[0]);
        v[1] = cs.y * (expf(dl.y) * inv[1]);
        v[2] = cs.z * (expf(dl.z) * inv[2]);
        v[3] = cs.w * (expf(dl.w) * inv[3]);
        *(float4 *)&out[(size_t)FS_OFF + i * 4] = make_float4(v[0], v[1], v[2], v[3]);
        float mean = 0.25f * (v[0] + v[1] + v[2] + v[3]);
        g_mean[i] = mean;
        v[4] = -mean;
#pragma unroll
        for (int e = 0; e < 5; e++) v[5+e] = g_ref1[(size_t)i*5+e];
#pragma unroll
        for (int e = 0; e < 5; e++) v[10+e] = g_ref2[(size_t)i*5+e];
#pragma unroll
        for (int c = 0; c < NC; c++) {
            fmn[c] = fminf(fmn[c], v[c]); fmx[c] = fmaxf(fmx[c], v[c]); fsm[c] += v[c];
        }
#pragma unroll
        for (int s = 0; s < NSEL; s++) {
            unsigned bucket = 0xFFFFFFFFu;
            if (incS[s]) bucket = encf(v[s]) >> 21;
            unsigned mm = __match_any_sync(0xffffffffu, bucket);
            int leader = __ffs(mm) - 1;
            if ((int)(tid & 31) == leader && bucket != 0xFFFFFFFFu)
                atomicAdd(&histS[s * 2048 + bucket], __popc(mm));
        }
    }
#pragma unroll
    for (int off = 16; off; off >>= 1)
#pragma unroll
        for (int c = 0; c < NC; c++) {
            fmn[c] = fminf(fmn[c], __shfl_xor_sync(0xffffffffu, fmn[c], off));
            fmx[c] = fmaxf(fmx[c], __shfl_xor_sync(0xffffffffu, fmx[c], off));
            fsm[c] += __shfl_xor_sync(0xffffffffu, fsm[c], off);
        }
    __shared__ float smn[8][NC], smx[8][NC], ssm[8][NC];
    int w = tid >> 5, l = tid & 31;
    if (l == 0) for (int c = 0; c < NC; c++) { smn[w][c]=fmn[c]; smx[w][c]=fmx[c]; ssm[w][c]=fsm[c]; }
    __syncthreads();
    if (tid == 0)
        for (int c = 0; c < NC; c++) {
            float a = smn[0][c], b = smx[0][c], s = ssm[0][c];
            for (int ww = 1; ww < 8; ww++) { a=fminf(a,smn[ww][c]); b=fmaxf(b,smx[ww][c]); s+=ssm[ww][c]; }
            atomicMin(&g_fs_min_enc[c], encf(a));
            atomicMax(&g_fs_max_enc[c], encf(b));
            atomicAdd(&g_fs_sum[c], s);
        }
    __syncthreads();
    for (int i = tid; i < NSEL * 2048; i += blockDim.x)
        if (histS[i]) atomicAdd(&g_hist[i / 2048][i % 2048], histS[i]);
}

__device__ __forceinline__ void load_vals(const float *__restrict__ outFS, int i, float v[NSEL]) {
    float4 fs = *(const float4 *)&outFS[i * 4];
    v[0]=fs.x; v[1]=fs.y; v[2]=fs.z; v[3]=fs.w;
    v[4] = -g_mean[i];
#pragma unroll
    for (int e = 0; e < 5; e++) v[5+e] = g_ref1[(size_t)i*5+e];
#pragma unroll
    for (int e = 0; e < 5; e++) v[10+e] = g_ref2[(size_t)i*5+e];
}

// radix passes 1,2 (bins 2048/1024, shifts 10/0)
__global__ void k_hist(const float *__restrict__ outFS, int pass) {
    extern __shared__ unsigned histS[];
    __shared__ unsigned prefS[NSEL];
    __shared__ int incS[NSEL];
    int tid = threadIdx.x;
    int bins = (pass == 2) ? 1024 : 2048;
    int shift = (pass == 1) ? 10 : 0;
    int prevsh = (pass == 1) ? 21 : 10;
    for (int i = tid; i < NSEL * bins; i += blockDim.x) histS[i] = 0u;
    if (tid < NSEL) { prefS[tid] = g_prefix[tid]; incS[tid] = g_include[tid]; }
    __syncthreads();
    for (int i = blockIdx.x * blockDim.x + tid; i < NI; i += gridDim.x * blockDim.x) {
        float v[NSEL];
        load_vals(outFS, i, v);
#pragma unroll
        for (int s = 0; s < NSEL; s++) {
            unsigned bucket = 0xFFFFFFFFu;
            if (incS[s]) {
                unsigned key = encf(v[s]);
                if ((key >> prevsh) == (prefS[s] >> prevsh))
                    bucket = (key >> shift) & (unsigned)(bins - 1);
            }
            unsigned mm = __match_any_sync(0xffffffffu, bucket);
            int leader = __ffs(mm) - 1;
            if ((int)(threadIdx.x & 31) == leader && bucket != 0xFFFFFFFFu)
                atomicAdd(&histS[s * bins + bucket], __popc(mm));
        }
    }
    __syncthreads();
    for (int i = tid; i < NSEL * bins; i += blockDim.x)
        if (histS[i]) atomicAdd(&g_hist[i / bins][i % bins], histS[i]);
}

__global__ void k_scan(int pass) {
    int w = threadIdx.x >> 5, l = threadIdx.x & 31;
    int bins = (pass == 2) ? 1024 : 2048;
    int shift = (pass == 0) ? 21 : (pass == 1) ? 10 : 0;
    if (w < NSEL && g_include[w]) {
        int kr = g_kRem[w];
        int chunk = bins >> 5;
        unsigned T = 0;
        for (int j = 0; j < chunk; j++) T += g_hist[w][l * chunk + j];
        unsigned x = T;
#pragma unroll
        for (int off = 1; off < 32; off <<= 1) {
            unsigned y = __shfl_down_sync(0xffffffffu, x, off);
            if (l + off < 32) x += y;
        }
        unsigned S = x - T;
        unsigned total = __shfl_sync(0xffffffffu, x, 0);
        bool has = (S < (unsigned)kr) && (S + T >= (unsigned)kr);
        unsigned bal = __ballot_sync(0xffffffffu, has);
        if (bal) {
            int selL = __ffs(bal) - 1;
            if (l == selL) {
                unsigned cum = S;
                for (int bin = (l + 1) * chunk - 1; bin >= l * chunk; bin--) {
                    unsigned c = g_hist[w][bin];
                    if (cum + c >= (unsigned)kr) {
                        g_prefix[w] |= ((unsigned)bin << shift);
                        g_kRem[w] = kr - (int)cum;
                        break;
                    }
                    cum += c;
                }
            }
        } else if (l == 0) {
            g_kRem[w] = kr - (int)total;
        }
    }
    __syncthreads();
    for (int i = threadIdx.x; i < NSEL * 2048; i += blockDim.x)
        ((unsigned *)g_hist)[i] = 0u;
}

__device__ __forceinline__ bool is_valid(int s, float v, const float *mn, const float *mx) {
    if (s < 4) return ((v - mn[s]) / (mx[s] - mn[s])) > 0.5f;
    else if (s == 4) return (-v) < 0.5f;
    else return v > 0.5f;
}

__global__ void k_gather(const float *__restrict__ outFS) {
    __shared__ float mnS[NC], mxS[NC];
    __shared__ unsigned thrS[NSEL];
    __shared__ int incS[NSEL];
    int tid = threadIdx.x;
    if (tid < NC) { mnS[tid] = decf(g_fs_min_enc[tid]); mxS[tid] = decf(g_fs_max_enc[tid]); }
    if (tid < NSEL) { thrS[tid] = g_prefix[tid]; incS[tid] = g_include[tid]; }
    __syncthreads();
    for (int i = blockIdx.x * blockDim.x + tid; i < NI; i += gridDim.x * blockDim.x) {
        float v[NSEL];
        load_vals(outFS, i, v);
#pragma unroll
        for (int s = 0; s < NSEL; s++) {
            if (!incS[s]) continue;
            unsigned key = encf(v[s]);
            if (key > thrS[s]) {
                if (is_valid(s, v[s], mnS, mxS)) {
                    int g = (s < 5) ? 0 : (s < 10 ? 1 : 2);
                    atomicAdd(&g_den[g], 1);
                    int slot = atomicAdd(&g_cand_cnt, 1);
                    if (slot < MAXCAND) { g_cand_s[slot] = s; g_cand_i[slot] = i; }
                }
            } else if (key == thrS[s]) {
                int slot = atomicAdd(&g_eq_cnt[s], 1);
                if (slot < MAXEQ) g_eq_idx[s][slot] = i;
            }
        }
    }
}

__global__ void k_tie() {
    int warp = threadIdx.x >> 5;
    int lane = threadIdx.x & 31;
    if (warp >= NSEL) return;
    int s = warp;
    if (!g_include[s]) return;
    int m = g_eq_cnt[s];
    if (m > MAXEQ) m = MAXEQ;
    int nt = g_kRem[s];
    if (m <= 0 || nt <= 0) return;
    float v = decf(g_prefix[s]);
    float mn[NC], mx[NC];
#pragma unroll
    for (int c = 0; c < NC; c++) { mn[c] = decf(g_fs_min_enc[c]); mx[c] = decf(g_fs_max_enc[c]); }
    if (!is_valid(s, v, mn, mx)) return;
    int g = (s < 5) ? 0 : (s < 10 ? 1 : 2);
    int prev = -1;
    for (int t = 0; t < nt; t++) {
        int best = 0x7FFFFFFF;
        for (int j = lane; j < m; j += 32) {
            int idx = g_eq_idx[s][j];
            if (idx > prev && idx < best) best = idx;
        }
#pragma unroll
        for (int off = 16; off; off >>= 1)
            best = min(best, __shfl_xor_sync(0xffffffffu, best, off));
        if (best == 0x7FFFFFFF) break;
        if (lane == 0) {
            atomicAdd(&g_den[g], 1);
            int slot = atomicAdd(&g_cand_cnt, 1);
            if (slot < MAXCAND) { g_cand_s[slot] = s; g_cand_i[slot] = best; }
        }
        prev = best;
    }
}

__global__ __launch_bounds__(128) void k_ce(const float *__restrict__ h,
                                            const float *__restrict__ Wr,
                                            const float *__restrict__ br) {
    __shared__ float WrS[3 * DD * 5];
    __shared__ float brS[15];
    __shared__ float red[4][5];
    int tid = threadIdx.x;
    for (int i = tid; i < 3 * DD * 5; i += 128) WrS[i] = Wr[i];
    if (tid < 15) brS[tid] = br[tid];
    __syncthreads();
    int cnt = g_cand_cnt;
    if (cnt > MAXCAND) cnt = MAXCAND;
    int warp = tid >> 5, lane = tid & 31;
    for (int ci = blockIdx.x; ci < cnt; ci += gridDim.x) {
        int s = g_cand_s[ci], i = g_cand_i[ci];
        int r = (s < 5) ? 0 : (s < 10 ? 1 : 2);
        int tgt = (s < 4) ? s : ((s == 4) ? 4 : (s - 5) % 5);
        const float *hr = h + (size_t)i * DD;
        float part[5] = {0.f, 0.f, 0.f, 0.f, 0.f};
#pragma unroll
        for (int t = 0; t < 4; t++) {
            float hv = hr[tid + 128 * t];
            const float *wk = &WrS[r * (DD * 5) + (tid + 128 * t) * 5];
#pragma unroll
            for (int e = 0; e < 5; e++) part[e] = fmaf(hv, wk[e], part[e]);
        }
#pragma unroll
        for (int off = 16; off; off >>= 1)
#pragma unroll
            for (int e = 0; e < 5; e++) part[e] += __shfl_xor_sync(0xffffffffu, part[e], off);
        if (lane == 0)
            for (int e = 0; e < 5; e++) red[warp][e] = part[e];
        __syncthreads();
        if (tid == 0) {
            float lv[5]; float mm = -1e30f;
#pragma unroll
            for (int e = 0; e < 5; e++) {
                lv[e] = red[0][e] + red[1][e] + red[2][e] + red[3][e] + brS[r * 5 + e];
                mm = fmaxf(mm, lv[e]);
            }
            float ss = 0.f;
#pragma unroll
            for (int e = 0; e < 5; e++) ss += expf(lv[e] - mm);
            float ce = logf(ss) + mm - lv[tgt];
            atomicAdd(&g_num[r], ce);
        }
        __syncthreads();
    }
}

__global__ void k_finish(float *__restrict__ out) {
    if (threadIdx.x == 0) {
        float yp[NC];
#pragma unroll
        for (int c = 0; c < NC; c++) {
            float v = g_fs_sum[c];
            v = fminf(fmaxf(v, 1e-10f), 1.f - 1e-10f);
            yp[c] = v;
            out[YP_OFF + c] = v;
        }
        int am = 0;
        for (int c = 1; c < NC; c++)
            if (yp[c] > yp[am]) am = c;
        out[YH_OFF] = (float)am;
        float loss = 0.f;
        for (int g = 0; g < 3; g++) {
            float den = (float)(g_den[g] > 1 ? g_den[g] : 1);
            loss += g_num[g] / den;
        }
        out[IL_OFF] = loss;
    }
}

extern "C" void kernel_launch(void *const *d_in, const int *in_sizes, int n_in,
                              void *d_out, int out_size) {
    const float *h    = (const float *)d_in[0];
    const int   *label= (const int *)d_in[1];
    const float *Wa   = (const float *)d_in[2];
    const float *ba   = (const float *)d_in[3];
    const float *Wb   = (const float *)d_in[4];
    const float *bb   = (const float *)d_in[5];
    const float *Wc   = (const float *)d_in[6];
    const float *bc   = (const float *)d_in[7];
    const float *Wcls = (const float *)d_in[8];
    const float *bcls = (const float *)d_in[9];
    const float *Wr   = (const float *)d_in[10];
    const float *br   = (const float *)d_in[11];
    float *out = (float *)d_out;

    cudaFuncSetAttribute(k1_mma, cudaFuncAttributeMaxDynamicSharedMemorySize, K1_SMEM);
    cudaFuncSetAttribute(k_hist, cudaFuncAttributeMaxDynamicSharedMemorySize, NSEL * 2048 * 4);
    cudaFuncSetAttribute(k_fscore, cudaFuncAttributeMaxDynamicSharedMemorySize, NSEL * 2048 * 4);

    k_init<<<1, 256>>>(label);
    k_wsplit<<<(512 * 512 + 32 * 512 + 255) / 256, 256>>>(Wa, Wb, Wcls, Wr, bc);
    k_split<<<(int)(((size_t)ROWS_PAD * DD / 8 + 255) / 256), 256>>>(h);
    k1_mma<<<TILES * 5, 256, K1_SMEM>>>(ba, bb, Wc, bcls, br, out + REF_OFF);  // 4th -> profiled
    k_detsum<<<256, 256>>>();
    k_fscore<<<148, 256, NSEL * 2048 * 4>>>(out);
    k_scan<<<1, 480>>>(0);
    k_hist<<<200, 256, NSEL * 2048 * 4>>>(out, 1);
    k_scan<<<1, 480>>>(1);
    k_hist<<<200, 256, NSEL * 1024 * 4>>>(out, 2);
    k_scan<<<1, 480>>>(2);
    k_gather<<<200, 256>>>(out);
    k_tie<<<1, 480>>>();
    k_ce<<<1024, 128>>>(h, Wr, br);
    k_finish<<<1, 1>>>(out);
}